// round 2
// baseline (speedup 1.0000x reference)
#include <cuda_runtime.h>

#define HH   1024
#define WW   1024
#define MAXB 8
#define WIN  51
#define HALF 25
#define NP   (HH + 2*HALF)   // 1074 padded row length

// ---------------- scratch (static device globals; no runtime alloc) ----------------
__device__ float        g_gray[(size_t)MAXB * HH * WW];
__device__ float2       g_sh  [(size_t)MAXB * HH * WW];   // (Sh, Sh2) horizontal 51-window sums
__device__ unsigned int g_minb, g_maxb;

// ---------------- kernel 0: reset global min/max (every graph replay) ----------------
__global__ void k_init()
{
    g_minb = 0x7F800000u;  // +inf bits (gray >= 0, uint order == float order)
    g_maxb = 0u;           // 0.0f
}

// ---------------- kernel 1: per-row gray + min/max + horizontal window sums ----------
__global__ __launch_bounds__(256) void k_row(const float* __restrict__ in)
{
    const int row = blockIdx.x;          // global row index 0 .. B*H-1
    const int tid = threadIdx.x;

    __shared__ float  s_rgb[3072];
    __shared__ float  s_gp[NP];          // reflect-padded gray row
    __shared__ double s_P1[NP + 1];      // exclusive prefix of gray
    __shared__ double s_P2[NP + 1];      // exclusive prefix of gray^2 (f32-squared)
    __shared__ double s_w1[8], s_w2[8];
    __shared__ float  s_mn[8], s_mx[8];

    // load full RGB row (12 KB) as float4
    const float4* in4 = (const float4*)(in + (size_t)row * (WW * 3));
    float4* s4 = (float4*)s_rgb;
    #pragma unroll
    for (int k = tid; k < 768; k += 256) s4[k] = in4[k];
    __syncthreads();

    // gray = 0.2989 r + 0.5870 g + 0.1140 b   (plain f32, no fma contraction)
    float lmin = 1e30f, lmax = -1e30f;
    float* grow = g_gray + (size_t)row * WW;
    #pragma unroll
    for (int i = tid; i < WW; i += 256) {
        float r = s_rgb[3*i], g = s_rgb[3*i+1], b = s_rgb[3*i+2];
        float gray = __fadd_rn(__fadd_rn(__fmul_rn(0.2989f, r),
                                         __fmul_rn(0.5870f, g)),
                               __fmul_rn(0.1140f, b));
        s_gp[HALF + i] = gray;
        grow[i] = gray;
        lmin = fminf(lmin, gray);
        lmax = fmaxf(lmax, gray);
    }
    __syncthreads();

    // reflect padding (numpy 'reflect': i<0 -> -i ; i>=N -> 2N-2-i)
    if (tid < HALF) s_gp[tid] = s_gp[2*HALF - tid];
    if (tid >= 32 && tid < 32 + HALF) {
        int p = (HH + HALF) + (tid - 32);          // 1049 .. 1073
        s_gp[p] = s_gp[2*(HH + HALF) - 2 - p];     // 2096 - p
    }
    __syncthreads();

    // block-wide exact double prefix scan over 1074 padded values (gray and gray^2)
    const int CH = 5;                    // 256 threads * 5 = 1280 >= 1074
    const int base = tid * CH;
    float  v[CH];
    double t1 = 0.0, t2 = 0.0;
    #pragma unroll
    for (int j = 0; j < CH; j++) {
        int idx = base + j;
        float x = (idx < NP) ? s_gp[idx] : 0.0f;
        v[j] = x;
        t1 += (double)x;
        t2 += (double)__fmul_rn(x, x);   // square in f32, like the reference
    }
    const int lane = tid & 31, wid = tid >> 5;
    double x1 = t1, x2 = t2;
    #pragma unroll
    for (int d = 1; d < 32; d <<= 1) {
        double y1 = __shfl_up_sync(0xFFFFFFFFu, x1, d);
        double y2 = __shfl_up_sync(0xFFFFFFFFu, x2, d);
        if (lane >= d) { x1 += y1; x2 += y2; }
    }
    if (lane == 31) { s_w1[wid] = x1; s_w2[wid] = x2; }
    __syncthreads();
    if (tid < 8) {
        double w1 = s_w1[tid], w2 = s_w2[tid];
        #pragma unroll
        for (int d = 1; d < 8; d <<= 1) {
            double y1 = __shfl_up_sync(0xFFu, w1, d);
            double y2 = __shfl_up_sync(0xFFu, w2, d);
            if (tid >= d) { w1 += y1; w2 += y2; }
        }
        s_w1[tid] = w1; s_w2[tid] = w2;
    }
    __syncthreads();
    double run1 = x1 - t1 + (wid ? s_w1[wid-1] : 0.0);
    double run2 = x2 - t2 + (wid ? s_w2[wid-1] : 0.0);
    #pragma unroll
    for (int j = 0; j < CH; j++) {
        int idx = base + j;
        if (idx < NP) {
            s_P1[idx] = run1;  s_P2[idx] = run2;
            run1 += (double)v[j];
            run2 += (double)__fmul_rn(v[j], v[j]);
        } else if (idx == NP) {
            s_P1[idx] = run1;  s_P2[idx] = run2;
        }
    }
    __syncthreads();

    // horizontal 51-window sums -> float2, coalesced
    float2* shrow = g_sh + (size_t)row * WW;
    #pragma unroll
    for (int i = tid; i < WW; i += 256) {
        float a = (float)(s_P1[i + WIN] - s_P1[i]);
        float b = (float)(s_P2[i + WIN] - s_P2[i]);
        shrow[i] = make_float2(a, b);
    }

    // global min/max reduce
    #pragma unroll
    for (int d = 16; d; d >>= 1) {
        lmin = fminf(lmin, __shfl_down_sync(0xFFFFFFFFu, lmin, d));
        lmax = fmaxf(lmax, __shfl_down_sync(0xFFFFFFFFu, lmax, d));
    }
    if (lane == 0) { s_mn[wid] = lmin; s_mx[wid] = lmax; }
    __syncthreads();
    if (tid == 0) {
        float mn = s_mn[0], mx = s_mx[0];
        #pragma unroll
        for (int i = 1; i < 8; i++) { mn = fminf(mn, s_mn[i]); mx = fmaxf(mx, s_mx[i]); }
        atomicMin(&g_minb, __float_as_uint(mn));
        atomicMax(&g_maxb, __float_as_uint(mx));
    }
}

// ---------------- kernel 2: vertical running window + Sauvola threshold --------------
#define SEG 128
#define TW  128

__global__ __launch_bounds__(128) void k_vert(float* __restrict__ out)
{
    const int col = blockIdx.x * TW + threadIdx.x;
    const int y0  = blockIdx.y * SEG;
    const size_t imgoff = (size_t)blockIdx.z * ((size_t)HH * WW);
    const float2* sh = g_sh   + imgoff;
    const float*  gr = g_gray + imgoff;
    float*        op = out    + imgoff;

    const float rmax = __uint_as_float(g_maxb);
    const float rmin = __uint_as_float(g_minb);
    const float rr   = __fmul_rn(0.5f, __fsub_rn(rmax, rmin));
    const float inv_r = 1.0f / rr;
    const float invN  = (float)(1.0 / (WIN * WIN));

    // prologue: window for output row y0 covers rows y0-25 .. y0+25 (reflected)
    double S1 = 0.0, S2 = 0.0;
    #pragma unroll 1
    for (int j = 0; j < WIN; j++) {
        int yy = y0 - HALF + j;
        yy = (yy < 0) ? -yy : yy;
        if (yy > HH - 1) yy = 2*(HH - 1) - yy;
        float2 vv = sh[(size_t)yy * WW + col];
        S1 += (double)vv.x;
        S2 += (double)vv.y;
    }

    #pragma unroll 2
    for (int t = 0; t < SEG; t++) {
        const int y = y0 + t;

        float m   = (float)S1 * invN;
        float m2  = (float)S2 * invN;
        float var = fmaxf(__fmaf_rn(-m, m, m2), 0.0f);
        float s   = sqrtf(var);
        float thr = m * (1.0f + 0.2f * (s * inv_r - 1.0f));

        float g = gr[(size_t)y * WW + col];
        op[(size_t)y * WW + col] = (g > thr) ? 1.0f : 0.0f;

        // slide window: add row y+26, drop row y-25 (reflect-mapped)
        int ye = y + HALF + 1; if (ye > HH - 1) ye = 2*(HH - 1) - ye;
        int yl = y - HALF;     if (yl < 0)      yl = -yl;
        float2 e = sh[(size_t)ye * WW + col];
        float2 l = sh[(size_t)yl * WW + col];
        S1 += (double)e.x - (double)l.x;
        S2 += (double)e.y - (double)l.y;
    }
}

// ---------------- launcher ----------------
extern "C" void kernel_launch(void* const* d_in, const int* in_sizes, int n_in,
                              void* d_out, int out_size)
{
    const float* in = (const float*)d_in[0];
    const int B = in_sizes[0] / (HH * WW * 3);

    k_init<<<1, 1>>>();
    k_row<<<B * HH, 256>>>(in);
    dim3 g2(WW / TW, HH / SEG, B);
    k_vert<<<g2, TW>>>((float*)d_out);
}